// round 9
// baseline (speedup 1.0000x reference)
#include <cuda_runtime.h>
#include <math.h>

#define BB 16
#define HH 96
#define WW 96
#define CC 128
#define HWSZ 9216           // H*W
#define NPIX 147456         // B*H*W
#define LN_EPS 1e-3f

// ---------------- scratch (device globals; no allocation allowed) -----------
__device__ float g_q[NPIX * CC];       // NHWC
__device__ float g_ctx[NPIX * CC];     // NCHW  (b,c,h,w)
__device__ float g_ctxall[NPIX * CC];  // NCHW
__device__ float g_gates[NPIX * 4];    // NHWC4
__device__ float g_xout[NPIX * CC];    // NHWC
__device__ float g_pool[BB * CC];
__device__ float g_cg[BB * CC];        // gelu(mean ctx3) per (b, c)

__device__ __forceinline__ float gelu_exact(float v) {
    return 0.5f * v * (1.0f + erff(v * 0.70710678118654752f));
}

// ---------------- zero pool accumulator -------------------------------------
__global__ void zero_pool_kernel() {
    int i = blockIdx.x * blockDim.x + threadIdx.x;
    if (i < BB * CC) g_pool[i] = 0.0f;
}

// ---------------- GEMM1: y = x @ Wf[:, :256] + bf ---------------------------
// BM=64, BN=128, BK=16, 256 threads, TM=4, TN=8.
// blockIdx.x == 0 -> q (NHWC), blockIdx.x == 1 -> ctx (NCHW).
__global__ __launch_bounds__(256) void gemm1_kernel(
    const float* __restrict__ x, const float* __restrict__ Wf,
    const float* __restrict__ bf)
{
    __shared__ float As[16][64];
    __shared__ float Bs[16][128];
    const int tid = threadIdx.x;
    const int tx = tid & 15, ty = tid >> 4;
    const int row0 = blockIdx.y * 64;
    const int n0 = blockIdx.x * 128;  // column offset into Wf (0 or 128)

    float acc[4][8];
#pragma unroll
    for (int i = 0; i < 4; i++)
#pragma unroll
        for (int j = 0; j < 8; j++) acc[i][j] = 0.0f;

    const int la_m = tid >> 2;         // 0..63
    const int la_k = (tid & 3) * 4;    // 0,4,8,12
    const int lb_k = tid >> 5;         // 0..7
    const int lb_n = (tid & 31) * 4;   // 0..124

    for (int k0 = 0; k0 < 128; k0 += 16) {
        float4 av = *(const float4*)(x + (size_t)(row0 + la_m) * CC + k0 + la_k);
        As[la_k + 0][la_m] = av.x;
        As[la_k + 1][la_m] = av.y;
        As[la_k + 2][la_m] = av.z;
        As[la_k + 3][la_m] = av.w;
#pragma unroll
        for (int pass = 0; pass < 2; pass++) {
            int kk = lb_k + pass * 8;
            float4 bv = *(const float4*)(Wf + (size_t)(k0 + kk) * 260 + n0 + lb_n);
            *(float4*)&Bs[kk][lb_n] = bv;
        }
        __syncthreads();
#pragma unroll
        for (int k = 0; k < 16; k++) {
            float4 a = *(const float4*)&As[k][ty * 4];
            float4 b0 = *(const float4*)&Bs[k][tx * 8];
            float4 b1 = *(const float4*)&Bs[k][tx * 8 + 4];
            float am[4] = {a.x, a.y, a.z, a.w};
            float bn[8] = {b0.x, b0.y, b0.z, b0.w, b1.x, b1.y, b1.z, b1.w};
#pragma unroll
            for (int i = 0; i < 4; i++)
#pragma unroll
                for (int j = 0; j < 8; j++) acc[i][j] = fmaf(am[i], bn[j], acc[i][j]);
        }
        __syncthreads();
    }

    const int colb = tx * 8;
    if (blockIdx.x == 0) {
        // q path: NHWC, bias bf[col]
        float bv[8];
#pragma unroll
        for (int j = 0; j < 8; j++) bv[j] = __ldg(bf + colb + j);
#pragma unroll
        for (int i = 0; i < 4; i++) {
            int r = row0 + ty * 4 + i;
            float4 o0 = {acc[i][0] + bv[0], acc[i][1] + bv[1], acc[i][2] + bv[2], acc[i][3] + bv[3]};
            float4 o1 = {acc[i][4] + bv[4], acc[i][5] + bv[5], acc[i][6] + bv[6], acc[i][7] + bv[7]};
            *(float4*)(g_q + (size_t)r * CC + colb) = o0;
            *(float4*)(g_q + (size_t)r * CC + colb + 4) = o1;
        }
    } else {
        // ctx path: NCHW, bias bf[128+col]
        const int b = row0 / HWSZ;
        const int p0 = row0 % HWSZ;
#pragma unroll
        for (int j = 0; j < 8; j++) {
            int col = colb + j;
            float bias = __ldg(bf + 128 + col);
            float4 v = {acc[0][j] + bias, acc[1][j] + bias, acc[2][j] + bias, acc[3][j] + bias};
            *(float4*)(g_ctx + (size_t)(b * CC + col) * HWSZ + p0 + ty * 4) = v;
        }
    }
}

// ---------------- gates: x @ Wf[:, 256:260] + bf[256:260] -------------------
// one warp per pixel, 8 pixels per 256-thread block
__global__ __launch_bounds__(256) void gates_kernel(
    const float* __restrict__ x, const float* __restrict__ Wf,
    const float* __restrict__ bf)
{
    const int warp = threadIdx.x >> 5, lane = threadIdx.x & 31;
    const int n = blockIdx.x * 8 + warp;
    float4 xv = *(const float4*)(x + (size_t)n * CC + lane * 4);
    float s0 = 0.f, s1 = 0.f, s2 = 0.f, s3 = 0.f;
    float xa[4] = {xv.x, xv.y, xv.z, xv.w};
#pragma unroll
    for (int t = 0; t < 4; t++) {
        int k = lane * 4 + t;
        const float* wrow = Wf + (size_t)k * 260 + 256;
        s0 = fmaf(xa[t], __ldg(wrow + 0), s0);
        s1 = fmaf(xa[t], __ldg(wrow + 1), s1);
        s2 = fmaf(xa[t], __ldg(wrow + 2), s2);
        s3 = fmaf(xa[t], __ldg(wrow + 3), s3);
    }
#pragma unroll
    for (int off = 16; off; off >>= 1) {
        s0 += __shfl_xor_sync(0xffffffffu, s0, off);
        s1 += __shfl_xor_sync(0xffffffffu, s1, off);
        s2 += __shfl_xor_sync(0xffffffffu, s2, off);
        s3 += __shfl_xor_sync(0xffffffffu, s3, off);
    }
    if (lane == 0) {
        float4 g = {s0 + __ldg(bf + 256), s1 + __ldg(bf + 257),
                    s2 + __ldg(bf + 258), s3 + __ldg(bf + 259)};
        *(float4*)(g_gates + (size_t)n * 4) = g;
    }
}

// ---------------- fused 3-level depthwise conv + gated accumulate -----------
// one block per (tile, channel, batch); 32x32 output tile, halo 6.
// IMPORTANT: halo values of ctx1/ctx2 that lie OUTSIDE the image must be zero
// (reference zero-pads each conv's input at the image boundary), not the
// "virtual" conv output computed from the zero-extended previous level.
__global__ __launch_bounds__(256) void conv_kernel(
    const float* __restrict__ kw0, const float* __restrict__ kw1,
    const float* __restrict__ kw2)
{
    __shared__ float buf0[44 * 44];
    __shared__ float buf1[42 * 42];
    __shared__ float buf2[38 * 38];
    __shared__ float wts[83];
    __shared__ float red[256];

    const int tid = threadIdx.x;
    const int tile = blockIdx.x;
    const int ty0 = (tile / 3) * 32, tx0 = (tile % 3) * 32;
    const int c = blockIdx.y, b = blockIdx.z;
    const float* src = g_ctx + (size_t)(b * CC + c) * HWSZ;

    if (tid < 9)       wts[tid] = __ldg(kw0 + tid * CC + c);
    else if (tid < 34) wts[tid] = __ldg(kw1 + (tid - 9) * CC + c);
    else if (tid < 83) wts[tid] = __ldg(kw2 + (tid - 34) * CC + c);

    for (int idx = tid; idx < 44 * 44; idx += 256) {
        int ly = idx / 44, lx = idx % 44;
        int gy = ty0 - 6 + ly, gx = tx0 - 6 + lx;
        float v = 0.0f;
        if (gy >= 0 && gy < HH && gx >= 0 && gx < WW) v = src[gy * WW + gx];
        buf0[idx] = v;
    }
    __syncthreads();

    // level 0: 3x3 -> ctx1 at global (ty0-5+oy, tx0-5+ox); zero outside image
    for (int idx = tid; idx < 42 * 42; idx += 256) {
        int oy = idx / 42, ox = idx % 42;
        int gy = ty0 - 5 + oy, gx = tx0 - 5 + ox;
        float s = 0.0f;
#pragma unroll
        for (int i = 0; i < 3; i++)
#pragma unroll
            for (int j = 0; j < 3; j++)
                s = fmaf(buf0[(oy + i) * 44 + ox + j], wts[i * 3 + j], s);
        bool inimg = (gy >= 0) & (gy < HH) & (gx >= 0) & (gx < WW);
        buf1[idx] = inimg ? gelu_exact(s) : 0.0f;
    }
    __syncthreads();

    // level 1: 5x5 -> ctx2 at global (ty0-3+oy, tx0-3+ox); zero outside image
    for (int idx = tid; idx < 38 * 38; idx += 256) {
        int oy = idx / 38, ox = idx % 38;
        int gy = ty0 - 3 + oy, gx = tx0 - 3 + ox;
        float s = 0.0f;
#pragma unroll
        for (int i = 0; i < 5; i++)
#pragma unroll
            for (int j = 0; j < 5; j++)
                s = fmaf(buf1[(oy + i) * 42 + ox + j], wts[9 + i * 5 + j], s);
        bool inimg = (gy >= 0) & (gy < HH) & (gx >= 0) & (gx < WW);
        buf2[idx] = inimg ? gelu_exact(s) : 0.0f;
    }
    __syncthreads();

    // level 2: 7x7 + gated accumulation + pooled sum of final ctx
    float psum = 0.0f;
    for (int idx = tid; idx < 32 * 32; idx += 256) {
        int oy = idx / 32, ox = idx % 32;
        float s = 0.0f;
#pragma unroll
        for (int i = 0; i < 7; i++)
#pragma unroll
            for (int j = 0; j < 7; j++)
                s = fmaf(buf2[(oy + i) * 38 + ox + j], wts[34 + i * 7 + j], s);
        float c3 = gelu_exact(s);
        psum += c3;
        int gy = ty0 + oy, gx = tx0 + ox;
        int n = b * HWSZ + gy * WW + gx;
        float4 g = *(const float4*)(g_gates + (size_t)n * 4);
        float val = buf1[(oy + 5) * 42 + (ox + 5)] * g.x
                  + buf2[(oy + 3) * 38 + (ox + 3)] * g.y
                  + c3 * g.z;
        g_ctxall[(size_t)(b * CC + c) * HWSZ + gy * WW + gx] = val;
    }

    red[tid] = psum;
    __syncthreads();
#pragma unroll
    for (int s = 128; s > 0; s >>= 1) {
        if (tid < s) red[tid] += red[tid + s];
        __syncthreads();
    }
    if (tid == 0) atomicAdd(&g_pool[b * CC + c], red[0]);
}

// ---------------- pooled-branch: cg = gelu(mean ctx3) -----------------------
__global__ void poolm_kernel() {
    const int b = blockIdx.x, t = threadIdx.x;
    g_cg[b * CC + t] = gelu_exact(g_pool[b * CC + t] * (1.0f / (float)HWSZ));
}

// ---------------- GEMM2: modulator + q-mult + LayerNorm ---------------------
// A[pix, c] = ctx_all + g3[pix] * cg[c], B = Wh. BM=64, BN=128, BK=16.
__global__ __launch_bounds__(256) void gemm2_kernel(
    const float* __restrict__ Wh, const float* __restrict__ bh,
    const float* __restrict__ gamma, const float* __restrict__ beta)
{
    __shared__ float As[16][64];
    __shared__ float Bs[16][128];
    __shared__ float sg3[64];
    __shared__ float scg[CC];
    __shared__ float redS[64][16];
    __shared__ float redQ[64][16];
    __shared__ float smu[64], srs[64];

    const int tid = threadIdx.x;
    const int tx = tid & 15, ty = tid >> 4;
    const int row0 = blockIdx.x * 64;
    const int b = row0 / HWSZ;
    const int p0 = row0 % HWSZ;

    if (tid < 64) sg3[tid] = g_gates[(size_t)(row0 + tid) * 4 + 3];
    else if (tid < 192) scg[tid - 64] = g_cg[b * CC + (tid - 64)];
    __syncthreads();

    float acc[4][8];
#pragma unroll
    for (int i = 0; i < 4; i++)
#pragma unroll
        for (int j = 0; j < 8; j++) acc[i][j] = 0.0f;

    const int la_k = tid >> 4;          // 0..15
    const int la_m = (tid & 15) * 4;    // 0..60
    const int lb_k = tid >> 5;          // 0..7
    const int lb_n = (tid & 31) * 4;

    for (int k0 = 0; k0 < 128; k0 += 16) {
        float4 av = *(const float4*)(g_ctxall + (size_t)(b * CC + k0 + la_k) * HWSZ + p0 + la_m);
        float cgk = scg[k0 + la_k];
        As[la_k][la_m + 0] = av.x + sg3[la_m + 0] * cgk;
        As[la_k][la_m + 1] = av.y + sg3[la_m + 1] * cgk;
        As[la_k][la_m + 2] = av.z + sg3[la_m + 2] * cgk;
        As[la_k][la_m + 3] = av.w + sg3[la_m + 3] * cgk;
#pragma unroll
        for (int pass = 0; pass < 2; pass++) {
            int kk = lb_k + pass * 8;
            *(float4*)&Bs[kk][lb_n] = *(const float4*)(Wh + (size_t)(k0 + kk) * CC + lb_n);
        }
        __syncthreads();
#pragma unroll
        for (int k = 0; k < 16; k++) {
            float4 a = *(const float4*)&As[k][ty * 4];
            float4 b0 = *(const float4*)&Bs[k][tx * 8];
            float4 b1 = *(const float4*)&Bs[k][tx * 8 + 4];
            float am[4] = {a.x, a.y, a.z, a.w};
            float bn[8] = {b0.x, b0.y, b0.z, b0.w, b1.x, b1.y, b1.z, b1.w};
#pragma unroll
            for (int i = 0; i < 4; i++)
#pragma unroll
                for (int j = 0; j < 8; j++) acc[i][j] = fmaf(am[i], bn[j], acc[i][j]);
        }
        __syncthreads();
    }

    const int colb = tx * 8;
    float bhv[8];
#pragma unroll
    for (int j = 0; j < 8; j++) bhv[j] = __ldg(bh + colb + j);

    float xo[4][8];
#pragma unroll
    for (int i = 0; i < 4; i++) {
        int r = row0 + ty * 4 + i;
        float4 q0 = *(const float4*)(g_q + (size_t)r * CC + colb);
        float4 q1 = *(const float4*)(g_q + (size_t)r * CC + colb + 4);
        float qa[8] = {q0.x, q0.y, q0.z, q0.w, q1.x, q1.y, q1.z, q1.w};
        float ps = 0.0f, pq = 0.0f;
#pragma unroll
        for (int j = 0; j < 8; j++) {
            float mod = acc[i][j] + bhv[j];
            float v = qa[j] * mod;
            xo[i][j] = v;
            ps += v;
            pq = fmaf(v, v, pq);
        }
        redS[ty * 4 + i][tx] = ps;
        redQ[ty * 4 + i][tx] = pq;
    }
    __syncthreads();
    if (tid < 64) {
        float s = 0.0f, sq = 0.0f;
#pragma unroll
        for (int t = 0; t < 16; t++) { s += redS[tid][t]; sq += redQ[tid][t]; }
        float mu = s * (1.0f / CC);
        float var = sq * (1.0f / CC) - mu * mu;
        smu[tid] = mu;
        srs[tid] = rsqrtf(var + LN_EPS);
    }
    __syncthreads();

    float gmv[8], bev[8];
#pragma unroll
    for (int j = 0; j < 8; j++) {
        gmv[j] = __ldg(gamma + colb + j);
        bev[j] = __ldg(beta + colb + j);
    }
#pragma unroll
    for (int i = 0; i < 4; i++) {
        int lr = ty * 4 + i;
        int r = row0 + lr;
        float mu = smu[lr], rs = srs[lr];
        float o[8];
#pragma unroll
        for (int j = 0; j < 8; j++) o[j] = fmaf((xo[i][j] - mu) * rs, gmv[j], bev[j]);
        *(float4*)(g_xout + (size_t)r * CC + colb) = make_float4(o[0], o[1], o[2], o[3]);
        *(float4*)(g_xout + (size_t)r * CC + colb + 4) = make_float4(o[4], o[5], o[6], o[7]);
    }
}

// ---------------- GEMM3: out = xout @ Wp + bp -------------------------------
__global__ __launch_bounds__(256) void gemm3_kernel(
    const float* __restrict__ Wp, const float* __restrict__ bp,
    float* __restrict__ out)
{
    __shared__ float As[16][64];
    __shared__ float Bs[16][128];
    const int tid = threadIdx.x;
    const int tx = tid & 15, ty = tid >> 4;
    const int row0 = blockIdx.x * 64;

    float acc[4][8];
#pragma unroll
    for (int i = 0; i < 4; i++)
#pragma unroll
        for (int j = 0; j < 8; j++) acc[i][j] = 0.0f;

    const int la_m = tid >> 2;
    const int la_k = (tid & 3) * 4;
    const int lb_k = tid >> 5;
    const int lb_n = (tid & 31) * 4;

    for (int k0 = 0; k0 < 128; k0 += 16) {
        float4 av = *(const float4*)(g_xout + (size_t)(row0 + la_m) * CC + k0 + la_k);
        As[la_k + 0][la_m] = av.x;
        As[la_k + 1][la_m] = av.y;
        As[la_k + 2][la_m] = av.z;
        As[la_k + 3][la_m] = av.w;
#pragma unroll
        for (int pass = 0; pass < 2; pass++) {
            int kk = lb_k + pass * 8;
            *(float4*)&Bs[kk][lb_n] = *(const float4*)(Wp + (size_t)(k0 + kk) * CC + lb_n);
        }
        __syncthreads();
#pragma unroll
        for (int k = 0; k < 16; k++) {
            float4 a = *(const float4*)&As[k][ty * 4];
            float4 b0 = *(const float4*)&Bs[k][tx * 8];
            float4 b1 = *(const float4*)&Bs[k][tx * 8 + 4];
            float am[4] = {a.x, a.y, a.z, a.w};
            float bn[8] = {b0.x, b0.y, b0.z, b0.w, b1.x, b1.y, b1.z, b1.w};
#pragma unroll
            for (int i = 0; i < 4; i++)
#pragma unroll
                for (int j = 0; j < 8; j++) acc[i][j] = fmaf(am[i], bn[j], acc[i][j]);
        }
        __syncthreads();
    }

    const int colb = tx * 8;
    float bv[8];
#pragma unroll
    for (int j = 0; j < 8; j++) bv[j] = __ldg(bp + colb + j);
#pragma unroll
    for (int i = 0; i < 4; i++) {
        int r = row0 + ty * 4 + i;
        float4 o0 = {acc[i][0] + bv[0], acc[i][1] + bv[1], acc[i][2] + bv[2], acc[i][3] + bv[3]};
        float4 o1 = {acc[i][4] + bv[4], acc[i][5] + bv[5], acc[i][6] + bv[6], acc[i][7] + bv[7]};
        *(float4*)(out + (size_t)r * CC + colb) = o0;
        *(float4*)(out + (size_t)r * CC + colb + 4) = o1;
    }
}

// ---------------- launcher ---------------------------------------------------
extern "C" void kernel_launch(void* const* d_in, const int* in_sizes, int n_in,
                              void* d_out, int out_size)
{
    const float *x = 0, *Wf = 0, *bf = 0, *Wh = 0, *bh = 0, *gamma = 0,
                *beta = 0, *Wp = 0, *bp = 0, *k0 = 0, *k1 = 0, *k2 = 0;
    int n16384 = 0, n128 = 0;
    for (int i = 0; i < n_in; i++) {
        const float* p = (const float*)d_in[i];
        switch (in_sizes[i]) {
            case 18874368: x = p; break;
            case 33280:    Wf = p; break;
            case 260:      bf = p; break;
            case 16384:    if (n16384++ == 0) Wh = p; else Wp = p; break;
            case 128:
                if (n128 == 0) bh = p;
                else if (n128 == 1) gamma = p;
                else if (n128 == 2) beta = p;
                else bp = p;
                n128++;
                break;
            case 1152:     k0 = p; break;
            case 3200:     k1 = p; break;
            case 6272:     k2 = p; break;
            default: break;
        }
    }
    float* out = (float*)d_out;

    zero_pool_kernel<<<8, 256>>>();
    gemm1_kernel<<<dim3(2, NPIX / 64), 256>>>(x, Wf, bf);
    gates_kernel<<<NPIX / 8, 256>>>(x, Wf, bf);
    conv_kernel<<<dim3(9, CC, BB), 256>>>(k0, k1, k2);
    poolm_kernel<<<BB, CC>>>();
    gemm2_kernel<<<NPIX / 64, 256>>>(Wh, bh, gamma, beta);
    gemm3_kernel<<<NPIX / 64, 256>>>(Wp, bp, out);
    (void)out_size;
}